// round 12
// baseline (speedup 1.0000x reference)
#include <cuda_runtime.h>
#include <cuda_fp16.h>
#include <math.h>
#include <stdint.h>

// Problem constants (BEVNet_26491358282245): x[2,160,160,128], qkv_w[384,128],
// proj_w[128,128], proj_b[128]. DILS=(1,2), KS=3, NH=8 -> hd=16, 4 heads/dilation.
#define B_ 2
#define H_ 160
#define W_ 160
#define C_ 128
#define NPIX (B_*H_*W_)   /* 51200 */

// Scratch (module-load allocated; no runtime alloc).
__device__ __half g_qkv[(size_t)NPIX * 384];   // [pix, 3*C] fp16 qkv
__device__ __half g_xh [(size_t)NPIX * 128];   // fp16 copy of x (QKV GEMM A)
__device__ __half g_att[(size_t)NPIX * 128];   // attention out, fp16 (proj GEMM A)
__device__ __half g_wq [384 * 128];            // fp16 qkv_w
__device__ __half g_wp [128 * 128];            // fp16 proj_w

// ---------------------------------------------------------------------------
// PTX helpers
// ---------------------------------------------------------------------------
__device__ __forceinline__ void mma_f16(
    float& c0, float& c1, float& c2, float& c3,
    uint32_t a0, uint32_t a1, uint32_t a2, uint32_t a3,
    uint32_t b0, uint32_t b1)
{
    asm volatile(
        "mma.sync.aligned.m16n8k16.row.col.f32.f16.f16.f32 "
        "{%0,%1,%2,%3}, {%4,%5,%6,%7}, {%8,%9}, {%0,%1,%2,%3};"
        : "+f"(c0), "+f"(c1), "+f"(c2), "+f"(c3)
        : "r"(a0), "r"(a1), "r"(a2), "r"(a3), "r"(b0), "r"(b1));
}

__device__ __forceinline__ void ldsm_x4(
    uint32_t& r0, uint32_t& r1, uint32_t& r2, uint32_t& r3, uint32_t addr)
{
    asm volatile("ldmatrix.sync.aligned.m8n8.x4.shared.b16 {%0,%1,%2,%3}, [%4];"
                 : "=r"(r0), "=r"(r1), "=r"(r2), "=r"(r3) : "r"(addr));
}

__device__ __forceinline__ void cp16(uint32_t smem_dst, const void* gptr) {
    asm volatile("cp.async.ca.shared.global [%0], [%1], 16;\n"
                 :: "r"(smem_dst), "l"(gptr));
}

__device__ __forceinline__ uint32_t pack_h2(float a, float b) {
    __half2 h = __floats2half2_rn(a, b);
    return *(uint32_t*)&h;
}

__device__ __forceinline__ float2 h2f(uint32_t u) {
    return __half22float2(*(__half2*)&u);
}

// ---------------------------------------------------------------------------
// Prep: convert x, qkv_w, proj_w to fp16 (vectorized, one launch).
// ---------------------------------------------------------------------------
#define XV (NPIX * 128 / 4)     /* 1638400 */
#define QV (384 * 128 / 4)      /* 12288 */
#define PV (128 * 128 / 4)      /* 4096 */

__global__ __launch_bounds__(256) void prep(
    const float4* __restrict__ x, const float4* __restrict__ qw,
    const float4* __restrict__ pw,
    uint2* __restrict__ xh, uint2* __restrict__ wq, uint2* __restrict__ wp)
{
    const int i = blockIdx.x * 256 + threadIdx.x;
    float4 v; uint2* dst;
    if (i < XV)                { v = x[i];            dst = xh + i; }
    else if (i < XV + QV)      { v = qw[i - XV];      dst = wq + (i - XV); }
    else if (i < XV + QV + PV) { v = pw[i - XV - QV]; dst = wp + (i - XV - QV); }
    else return;
    uint2 o;
    o.x = pack_h2(v.x, v.y);
    o.y = pack_h2(v.z, v.w);
    *dst = o;
}

// ---------------------------------------------------------------------------
// fp16 tensor-core GEMM, SINGLE-STAGE full-K: BM=BN=128, K=128 entirely in
// smem. One cp.async volley + one barrier, then 8 k16 steps of pure
// LDSM+MMA (no mid-loop barriers). Smem row stride 136 halves (68 words
// = 4 mod 32 -> ldmatrix tiles all 32 banks, conflict-free).
// C = A[M,128] * Bw[N,128]^T (+bias). OUT_HALF: pack epilogue to fp16.
// 256 threads, 8 warps 4(M)x2(N), warp tile 32x64.
// ---------------------------------------------------------------------------
#define SMPh 136

template<bool OUT_HALF>
__global__ __launch_bounds__(256, 2) void tgemm_h(
    const __half* __restrict__ A,
    const __half* __restrict__ Bw,
    const float* __restrict__ bias,
    void* __restrict__ Cv,
    int M, int N)
{
    __shared__ __align__(16) __half As[128 * SMPh];
    __shared__ __align__(16) __half Bs[128 * SMPh];

    const int bm   = blockIdx.x * 128;
    const int bn   = blockIdx.y * 128;
    const int tid  = threadIdx.x;
    const int wid  = tid >> 5;
    const int lane = tid & 31;
    const int wm   = (wid & 3) * 32;   // warp M offset
    const int wn   = (wid >> 2) * 64;  // warp N offset
    const int grp  = lane >> 2;
    const int tg   = lane & 3;

    // Loaders: row = tid>>1, 64-half slice = (tid&1); 8 cp16 per operand.
    const int lr = tid >> 1;
    const int lc = (tid & 1) * 64;
    const __half* Ag = A  + (size_t)(bm + lr) * 128 + lc;
    const __half* Bg = Bw + (size_t)(bn + lr) * 128 + lc;
    const uint32_t sa = (uint32_t)__cvta_generic_to_shared(&As[lr * SMPh + lc]);
    const uint32_t sb = (uint32_t)__cvta_generic_to_shared(&Bs[lr * SMPh + lc]);
    #pragma unroll
    for (int j = 0; j < 8; j++) {
        cp16(sa + j * 16, Ag + j * 8);
        cp16(sb + j * 16, Bg + j * 8);
    }
    asm volatile("cp.async.commit_group;\n" ::: "memory");

    // ldmatrix per-lane addresses.
    const uint32_t aBase = (uint32_t)__cvta_generic_to_shared(&As[0])
        + (uint32_t)(((wm + (((lane >> 3) & 1) * 8) + (lane & 7)) * SMPh
                      + ((lane >> 4) & 1) * 8) * 2);
    const uint32_t bBase = (uint32_t)__cvta_generic_to_shared(&Bs[0])
        + (uint32_t)(((wn + (((lane >> 4) & 1) * 8) + (lane & 7)) * SMPh
                      + ((lane >> 3) & 1) * 8) * 2);

    float acc[2][8][4];
    #pragma unroll
    for (int i = 0; i < 2; i++)
        #pragma unroll
        for (int j = 0; j < 8; j++)
            #pragma unroll
            for (int q = 0; q < 4; q++) acc[i][j][q] = 0.f;

    asm volatile("cp.async.wait_group 0;\n" ::: "memory");
    __syncthreads();

    // 8 k16 steps, no barriers.
    #pragma unroll
    for (int ks = 0; ks < 8; ks++) {
        const uint32_t kb = (uint32_t)ks * 32;   // 16 halves = 32B

        uint32_t afr[2][4];
        #pragma unroll
        for (int i = 0; i < 2; i++)
            ldsm_x4(afr[i][0], afr[i][1], afr[i][2], afr[i][3],
                    aBase + kb + (uint32_t)i * (16 * SMPh * 2));
        uint32_t bfr[8][2];
        #pragma unroll
        for (int jj = 0; jj < 4; jj++)
            ldsm_x4(bfr[2*jj][0], bfr[2*jj][1], bfr[2*jj+1][0], bfr[2*jj+1][1],
                    bBase + kb + (uint32_t)jj * (16 * SMPh * 2));

        #pragma unroll
        for (int i = 0; i < 2; i++)
            #pragma unroll
            for (int j = 0; j < 8; j++)
                mma_f16(acc[i][j][0], acc[i][j][1], acc[i][j][2], acc[i][j][3],
                        afr[i][0], afr[i][1], afr[i][2], afr[i][3],
                        bfr[j][0], bfr[j][1]);
    }

    #pragma unroll
    for (int j = 0; j < 8; j++) {
        const int col = bn + wn + j * 8 + 2 * tg;
        float b0 = bias ? bias[col]     : 0.f;
        float b1 = bias ? bias[col + 1] : 0.f;
        #pragma unroll
        for (int i = 0; i < 2; i++) {
            const int r0 = bm + wm + i * 16 + grp;
            if (OUT_HALF) {
                __half* Ch = (__half*)Cv;
                *(uint32_t*)(Ch + (size_t)r0 * N + col) =
                    pack_h2(acc[i][j][0] + b0, acc[i][j][1] + b1);
                *(uint32_t*)(Ch + (size_t)(r0 + 8) * N + col) =
                    pack_h2(acc[i][j][2] + b0, acc[i][j][3] + b1);
            } else {
                float* C = (float*)Cv;
                *(float2*)(C + (size_t)r0 * N + col) =
                    make_float2(acc[i][j][0] + b0, acc[i][j][1] + b1);
                *(float2*)(C + (size_t)(r0 + 8) * N + col) =
                    make_float2(acc[i][j][2] + b0, acc[i][j][3] + b1);
            }
        }
    }
}

// ---------------------------------------------------------------------------
// Fast exp on the FMA pipe (no MUFU). Scores are small; softmax shift-inv.
// ---------------------------------------------------------------------------
__device__ __forceinline__ float fast_exp(float x) {
    const float t = x * 1.4426950408889634f;
    const float z = t + 12582912.f;                  // 2^23 + 2^22
    const int   n = __float_as_int(z) - 0x4B400000;
    const float f = t - (z - 12582912.f);            // f in [-0.5, 0.5]
    float p = 9.6784100e-3f;
    p = fmaf(p, f, 5.5504110e-2f);
    p = fmaf(p, f, 2.4022651e-1f);
    p = fmaf(p, f, 6.9314718e-1f);
    p = fmaf(p, f, 1.0f);
    return __int_as_float(__float_as_int(p) + (n << 23));
}

// ---------------------------------------------------------------------------
// Dilated 3x3 neighborhood attention body (compile-time R), fp16 qkv input.
// Block = 16x16 pixel tile x (dilation, head). Smem stays fp32 (proven
// conflict-free layout); h2->f32 conversion happens during staging.
// ---------------------------------------------------------------------------
template<int R>
__device__ __forceinline__ void attn_body(
    const __half* __restrict__ qkv, __half* __restrict__ att, float* sm)
{
    constexpr int TW = 16 + 2 * R;
    constexpr int NR = TW * TW;

    const int tile = blockIdx.x;
    const int b    = blockIdx.y;
    const int hh   = blockIdx.z & 3;
    const int di   = (R == 1) ? 0 : 1;
    const int tx0  = (tile % 10) * 16;
    const int ty0  = (tile / 10) * 16;
    const int tid  = threadIdx.x;
    const int lx   = tid & 15;
    const int ly   = tid >> 4;
    const int off  = di * 64 + hh * 16;

    const size_t pix = ((size_t)b * H_ + (ty0 + ly)) * W_ + (tx0 + lx);

    // Load q (16 halves = one uint4), convert to 4 float4.
    const uint4 qr = *(const uint4*)(qkv + pix * 384 + off);
    const float2 f0 = h2f(qr.x), f1 = h2f(qr.y), f2 = h2f(qr.z), f3 = h2f(qr.w);
    const uint4 qr2 = *(const uint4*)(qkv + pix * 384 + off + 8);
    const float2 f4 = h2f(qr2.x), f5 = h2f(qr2.y), f6 = h2f(qr2.z), f7 = h2f(qr2.w);
    const float4 q0 = make_float4(f0.x, f0.y, f1.x, f1.y);
    const float4 q1 = make_float4(f2.x, f2.y, f3.x, f3.y);
    const float4 q2 = make_float4(f4.x, f4.y, f5.x, f5.y);
    const float4 q3 = make_float4(f6.x, f6.y, f7.x, f7.y);

    // Phase 1: K halo tile -> smem (zero fill OOB == reference zero padding).
    #pragma unroll 2
    for (int i = tid; i < NR * 2; i += 256) {
        const int row = i >> 1, h8 = (i & 1) * 8;
        const int lyy = row / TW, lxx = row - lyy * TW;
        const int yy = ty0 + lyy - R, xx = tx0 + lxx - R;
        float4 va = make_float4(0.f,0.f,0.f,0.f), vb = va;
        if (yy >= 0 && yy < H_ && xx >= 0 && xx < W_) {
            const uint4 u = *(const uint4*)(qkv
                + (((size_t)b * H_ + yy) * W_ + xx) * 384 + 128 + off + h8);
            const float2 a = h2f(u.x), c = h2f(u.y), d = h2f(u.z), e = h2f(u.w);
            va = make_float4(a.x, a.y, c.x, c.y);
            vb = make_float4(d.x, d.y, e.x, e.y);
        }
        *(float4*)&sm[row * 20 + h8]     = va;
        *(float4*)&sm[row * 20 + h8 + 4] = vb;
    }
    __syncthreads();

    float s[9];
    #pragma unroll
    for (int ky = 0; ky < 3; ky++)
        #pragma unroll
        for (int kx = 0; kx < 3; kx++) {
            const float* kp = &sm[((ly + ky * R) * TW + (lx + kx * R)) * 20];
            const float4 k0 = *(const float4*)(kp);
            const float4 k1 = *(const float4*)(kp + 4);
            const float4 k2 = *(const float4*)(kp + 8);
            const float4 k3 = *(const float4*)(kp + 12);
            float sc = q0.x*k0.x + q0.y*k0.y + q0.z*k0.z + q0.w*k0.w
                     + q1.x*k1.x + q1.y*k1.y + q1.z*k1.z + q1.w*k1.w
                     + q2.x*k2.x + q2.y*k2.y + q2.z*k2.z + q2.w*k2.w
                     + q3.x*k3.x + q3.y*k3.y + q3.z*k3.z + q3.w*k3.w;
            s[ky * 3 + kx] = sc * 0.25f;
        }

    float sum = 0.f;
    #pragma unroll
    for (int kk = 0; kk < 9; kk++) { s[kk] = fast_exp(s[kk]); sum += s[kk]; }
    const float inv = 1.f / sum;
    #pragma unroll
    for (int kk = 0; kk < 9; kk++) s[kk] *= inv;

    __syncthreads();

    // Phase 2: V halo tile -> same smem.
    #pragma unroll 2
    for (int i = tid; i < NR * 2; i += 256) {
        const int row = i >> 1, h8 = (i & 1) * 8;
        const int lyy = row / TW, lxx = row - lyy * TW;
        const int yy = ty0 + lyy - R, xx = tx0 + lxx - R;
        float4 va = make_float4(0.f,0.f,0.f,0.f), vb = va;
        if (yy >= 0 && yy < H_ && xx >= 0 && xx < W_) {
            const uint4 u = *(const uint4*)(qkv
                + (((size_t)b * H_ + yy) * W_ + xx) * 384 + 256 + off + h8);
            const float2 a = h2f(u.x), c = h2f(u.y), d = h2f(u.z), e = h2f(u.w);
            va = make_float4(a.x, a.y, c.x, c.y);
            vb = make_float4(d.x, d.y, e.x, e.y);
        }
        *(float4*)&sm[row * 20 + h8]     = va;
        *(float4*)&sm[row * 20 + h8 + 4] = vb;
    }
    __syncthreads();

    float4 o0 = {0,0,0,0}, o1 = {0,0,0,0}, o2 = {0,0,0,0}, o3 = {0,0,0,0};
    #pragma unroll
    for (int ky = 0; ky < 3; ky++)
        #pragma unroll
        for (int kx = 0; kx < 3; kx++) {
            const float w = s[ky * 3 + kx];
            const float* vp = &sm[((ly + ky * R) * TW + (lx + kx * R)) * 20];
            const float4 v0 = *(const float4*)(vp);
            const float4 v1 = *(const float4*)(vp + 4);
            const float4 v2 = *(const float4*)(vp + 8);
            const float4 v3 = *(const float4*)(vp + 12);
            o0.x += w*v0.x; o0.y += w*v0.y; o0.z += w*v0.z; o0.w += w*v0.w;
            o1.x += w*v1.x; o1.y += w*v1.y; o1.z += w*v1.z; o1.w += w*v1.w;
            o2.x += w*v2.x; o2.y += w*v2.y; o2.z += w*v2.z; o2.w += w*v2.w;
            o3.x += w*v3.x; o3.y += w*v3.y; o3.z += w*v3.z; o3.w += w*v3.w;
        }

    // Store fp16 (proj GEMM A operand). 16 halves = two uint4.
    uint4 u0, u1;
    u0.x = pack_h2(o0.x, o0.y); u0.y = pack_h2(o0.z, o0.w);
    u0.z = pack_h2(o1.x, o1.y); u0.w = pack_h2(o1.z, o1.w);
    u1.x = pack_h2(o2.x, o2.y); u1.y = pack_h2(o2.z, o2.w);
    u1.z = pack_h2(o3.x, o3.y); u1.w = pack_h2(o3.z, o3.w);
    uint4* op = (uint4*)(att + pix * 128 + off);
    op[0] = u0; op[1] = u1;
}

// One launch covering both dilations: grid z in 0..7, di = z>>2, head = z&3.
__global__ __launch_bounds__(256) void attn_all(
    const __half* __restrict__ qkv, __half* __restrict__ att)
{
    __shared__ float sm[20 * 20 * 20];   // sized for r=2 halo (400 rows x 20)
    if (blockIdx.z < 4) attn_body<1>(qkv, att, sm);
    else                attn_body<2>(qkv, att, sm);
}

// ---------------------------------------------------------------------------
extern "C" void kernel_launch(void* const* d_in, const int* in_sizes, int n_in,
                              void* d_out, int out_size)
{
    const float* x      = (const float*)d_in[0];
    const float* qkv_w  = (const float*)d_in[1];
    const float* proj_w = (const float*)d_in[2];
    const float* proj_b = (const float*)d_in[3];
    float* out = (float*)d_out;

    __half *qkvbuf, *xh, *attbuf, *wq, *wp;
    cudaGetSymbolAddress((void**)&qkvbuf, g_qkv);
    cudaGetSymbolAddress((void**)&xh, g_xh);
    cudaGetSymbolAddress((void**)&attbuf, g_att);
    cudaGetSymbolAddress((void**)&wq, g_wq);
    cudaGetSymbolAddress((void**)&wp, g_wp);

    // 0) Convert x + weights to fp16 (one vectorized launch).
    prep<<<(XV + QV + PV) / 256, 256>>>(
        (const float4*)x, (const float4*)qkv_w, (const float4*)proj_w,
        (uint2*)xh, (uint2*)wq, (uint2*)wp);

    // 1) QKV projection: [51200,128] x [384,128]^T -> [51200,384] fp16 out.
    dim3 g1(NPIX / 128, 384 / 128);
    tgemm_h<true><<<g1, 256>>>(xh, wq, nullptr, qkvbuf, NPIX, 384);

    // 2) Dilated neighborhood attention (both dilations, one launch; fp16 out)
    dim3 ga(100, 2, 8);
    attn_all<<<ga, 256>>>(qkvbuf, attbuf);

    // 3) Output projection + bias: [51200,128] x [128,128]^T -> fp32 out.
    dim3 g3(NPIX / 128, 128 / 128);
    tgemm_h<false><<<g3, 256>>>(attbuf, wp, proj_b, out, NPIX, 128);
}

// round 13
// speedup vs baseline: 1.1498x; 1.1498x over previous
#include <cuda_runtime.h>
#include <cuda_fp16.h>
#include <math.h>
#include <stdint.h>

// Problem constants (BEVNet_26491358282245): x[2,160,160,128], qkv_w[384,128],
// proj_w[128,128], proj_b[128]. DILS=(1,2), KS=3, NH=8 -> hd=16, 4 heads/dilation.
#define B_ 2
#define H_ 160
#define W_ 160
#define C_ 128
#define NPIX (B_*H_*W_)   /* 51200 */

// Scratch (module-load allocated; no runtime alloc).
__device__ __half g_qkv[(size_t)NPIX * 384];   // [pix, 3*C] fp16 qkv
__device__ __half g_xh [(size_t)NPIX * 128];   // fp16 copy of x (QKV GEMM A)
__device__ __half g_att[(size_t)NPIX * 128];   // attention out, fp16 (proj GEMM A)
__device__ __half g_wq [384 * 128];            // fp16 qkv_w
__device__ __half g_wp [128 * 128];            // fp16 proj_w

// ---------------------------------------------------------------------------
// PTX helpers
// ---------------------------------------------------------------------------
__device__ __forceinline__ void mma_f16(
    float& c0, float& c1, float& c2, float& c3,
    uint32_t a0, uint32_t a1, uint32_t a2, uint32_t a3,
    uint32_t b0, uint32_t b1)
{
    asm volatile(
        "mma.sync.aligned.m16n8k16.row.col.f32.f16.f16.f32 "
        "{%0,%1,%2,%3}, {%4,%5,%6,%7}, {%8,%9}, {%0,%1,%2,%3};"
        : "+f"(c0), "+f"(c1), "+f"(c2), "+f"(c3)
        : "r"(a0), "r"(a1), "r"(a2), "r"(a3), "r"(b0), "r"(b1));
}

__device__ __forceinline__ void ldsm_x4(
    uint32_t& r0, uint32_t& r1, uint32_t& r2, uint32_t& r3, uint32_t addr)
{
    asm volatile("ldmatrix.sync.aligned.m8n8.x4.shared.b16 {%0,%1,%2,%3}, [%4];"
                 : "=r"(r0), "=r"(r1), "=r"(r2), "=r"(r3) : "r"(addr));
}

__device__ __forceinline__ void cp16(uint32_t smem_dst, const void* gptr) {
    asm volatile("cp.async.ca.shared.global [%0], [%1], 16;\n"
                 :: "r"(smem_dst), "l"(gptr));
}

__device__ __forceinline__ uint32_t pack_h2(float a, float b) {
    __half2 h = __floats2half2_rn(a, b);
    return *(uint32_t*)&h;
}

__device__ __forceinline__ float2 h2f(uint32_t u) {
    return __half22float2(*(__half2*)&u);
}

// ---------------------------------------------------------------------------
// Prep: convert x, qkv_w, proj_w to fp16 (vectorized, one launch).
// ---------------------------------------------------------------------------
#define XV (NPIX * 128 / 4)     /* 1638400 */
#define QV (384 * 128 / 4)      /* 12288 */
#define PV (128 * 128 / 4)      /* 4096 */

__global__ __launch_bounds__(256) void prep(
    const float4* __restrict__ x, const float4* __restrict__ qw,
    const float4* __restrict__ pw,
    uint2* __restrict__ xh, uint2* __restrict__ wq, uint2* __restrict__ wp)
{
    const int i = blockIdx.x * 256 + threadIdx.x;
    float4 v; uint2* dst;
    if (i < XV)                { v = x[i];            dst = xh + i; }
    else if (i < XV + QV)      { v = qw[i - XV];      dst = wq + (i - XV); }
    else if (i < XV + QV + PV) { v = pw[i - XV - QV]; dst = wp + (i - XV - QV); }
    else return;
    uint2 o;
    o.x = pack_h2(v.x, v.y);
    o.y = pack_h2(v.z, v.w);
    *dst = o;
}

// ---------------------------------------------------------------------------
// fp16 tensor-core GEMM: BM=BN=128, BK=32, 3-stage cp.async, ldmatrix frags,
// mma.m16n8k16 fp32 accumulate. (R11 design — measured best.)
// C = A[M,128] * Bw[N,128]^T (+ bias). OUT_HALF: pack epilogue to fp16.
// 256 threads, 8 warps 4(M)x2(N), warp tile 32x64. 4 K-stages.
// ---------------------------------------------------------------------------
#define SMPh 40

template<bool OUT_HALF>
__global__ __launch_bounds__(256, 2) void tgemm_h(
    const __half* __restrict__ A,
    const __half* __restrict__ Bw,
    const float* __restrict__ bias,
    void* __restrict__ Cv,
    int M, int N)
{
    __shared__ __align__(16) __half As[3][128 * SMPh];
    __shared__ __align__(16) __half Bs[3][128 * SMPh];
    constexpr uint32_t STG = 128 * SMPh * 2;   // per-stage stride bytes

    const int bm   = blockIdx.x * 128;
    const int bn   = blockIdx.y * 128;
    const int tid  = threadIdx.x;
    const int wid  = tid >> 5;
    const int lane = tid & 31;
    const int wm   = (wid & 3) * 32;   // warp M offset
    const int wn   = (wid >> 2) * 64;  // warp N offset
    const int grp  = lane >> 2;
    const int tg   = lane & 3;

    // Global loaders: 128 rows x 32 halves; row tid>>1, 16-half slice tid&1.
    const int lr = tid >> 1;
    const int lc = (tid & 1) * 16;
    const __half* Ag = A  + (size_t)(bm + lr) * 128 + lc;
    const __half* Bg = Bw + (size_t)(bn + lr) * 128 + lc;
    const uint32_t sa0 = (uint32_t)__cvta_generic_to_shared(&As[0][lr * SMPh + lc]);
    const uint32_t sb0 = (uint32_t)__cvta_generic_to_shared(&Bs[0][lr * SMPh + lc]);

    // ldmatrix per-lane addresses.
    const uint32_t aBase = (uint32_t)__cvta_generic_to_shared(&As[0][0])
        + (uint32_t)(((wm + (((lane >> 3) & 1) * 8) + (lane & 7)) * SMPh
                      + ((lane >> 4) & 1) * 8) * 2);
    const uint32_t bBase = (uint32_t)__cvta_generic_to_shared(&Bs[0][0])
        + (uint32_t)(((wn + (((lane >> 4) & 1) * 8) + (lane & 7)) * SMPh
                      + ((lane >> 3) & 1) * 8) * 2);

    float acc[2][8][4];
    #pragma unroll
    for (int i = 0; i < 2; i++)
        #pragma unroll
        for (int j = 0; j < 8; j++)
            #pragma unroll
            for (int q = 0; q < 4; q++) acc[i][j][q] = 0.f;

    // Preload stages 0, 1 (k0 = 0, 32).
    cp16(sa0, Ag);            cp16(sa0 + 16, Ag + 8);
    cp16(sb0, Bg);            cp16(sb0 + 16, Bg + 8);
    asm volatile("cp.async.commit_group;\n" ::: "memory");
    cp16(sa0 + STG, Ag + 32); cp16(sa0 + STG + 16, Ag + 40);
    cp16(sb0 + STG, Bg + 32); cp16(sb0 + STG + 16, Bg + 40);
    asm volatile("cp.async.commit_group;\n" ::: "memory");

    #pragma unroll
    for (int t = 0; t < 4; t++) {
        asm volatile("cp.async.wait_group 1;\n" ::: "memory");
        __syncthreads();

        if (t < 2) {
            const int k0 = (t + 2) * 32;
            const uint32_t so = (uint32_t)((t + 2) % 3) * STG;
            cp16(sa0 + so, Ag + k0);  cp16(sa0 + so + 16, Ag + k0 + 8);
            cp16(sb0 + so, Bg + k0);  cp16(sb0 + so + 16, Bg + k0 + 8);
        }
        asm volatile("cp.async.commit_group;\n" ::: "memory");

        const uint32_t soff = (uint32_t)(t % 3) * STG;

        // Two k16 steps per stage.
        #pragma unroll
        for (int ks = 0; ks < 2; ks++) {
            const uint32_t kb = soff + (uint32_t)ks * 32;   // 16 halves = 32B

            uint32_t afr[2][4];
            #pragma unroll
            for (int i = 0; i < 2; i++)
                ldsm_x4(afr[i][0], afr[i][1], afr[i][2], afr[i][3],
                        aBase + kb + (uint32_t)i * (16 * SMPh * 2));
            uint32_t bfr[8][2];
            #pragma unroll
            for (int jj = 0; jj < 4; jj++)
                ldsm_x4(bfr[2*jj][0], bfr[2*jj][1], bfr[2*jj+1][0], bfr[2*jj+1][1],
                        bBase + kb + (uint32_t)jj * (16 * SMPh * 2));

            #pragma unroll
            for (int i = 0; i < 2; i++)
                #pragma unroll
                for (int j = 0; j < 8; j++)
                    mma_f16(acc[i][j][0], acc[i][j][1], acc[i][j][2], acc[i][j][3],
                            afr[i][0], afr[i][1], afr[i][2], afr[i][3],
                            bfr[j][0], bfr[j][1]);
        }
    }

    #pragma unroll
    for (int j = 0; j < 8; j++) {
        const int col = bn + wn + j * 8 + 2 * tg;
        float b0 = bias ? bias[col]     : 0.f;
        float b1 = bias ? bias[col + 1] : 0.f;
        #pragma unroll
        for (int i = 0; i < 2; i++) {
            const int r0 = bm + wm + i * 16 + grp;
            if (OUT_HALF) {
                __half* Ch = (__half*)Cv;
                *(uint32_t*)(Ch + (size_t)r0 * N + col) =
                    pack_h2(acc[i][j][0] + b0, acc[i][j][1] + b1);
                *(uint32_t*)(Ch + (size_t)(r0 + 8) * N + col) =
                    pack_h2(acc[i][j][2] + b0, acc[i][j][3] + b1);
            } else {
                float* C = (float*)Cv;
                *(float2*)(C + (size_t)r0 * N + col) =
                    make_float2(acc[i][j][0] + b0, acc[i][j][1] + b1);
                *(float2*)(C + (size_t)(r0 + 8) * N + col) =
                    make_float2(acc[i][j][2] + b0, acc[i][j][3] + b1);
            }
        }
    }
}

// ---------------------------------------------------------------------------
// Fast exp on the FMA pipe (no MUFU). Scores are small; softmax shift-inv.
// ---------------------------------------------------------------------------
__device__ __forceinline__ float fast_exp(float x) {
    const float t = x * 1.4426950408889634f;
    const float z = t + 12582912.f;                  // 2^23 + 2^22
    const int   n = __float_as_int(z) - 0x4B400000;
    const float f = t - (z - 12582912.f);            // f in [-0.5, 0.5]
    float p = 9.6784100e-3f;
    p = fmaf(p, f, 5.5504110e-2f);
    p = fmaf(p, f, 2.4022651e-1f);
    p = fmaf(p, f, 6.9314718e-1f);
    p = fmaf(p, f, 1.0f);
    return __int_as_float(__float_as_int(p) + (n << 23));
}

// ---------------------------------------------------------------------------
// Dilated 3x3 neighborhood attention body (compile-time R), fp16 qkv input.
// Block = 16x16 pixel tile x (dilation, head). Smem stays fp32 (proven
// conflict-free layout); h2->f32 conversion happens during staging.
// ---------------------------------------------------------------------------
template<int R>
__device__ __forceinline__ void attn_body(
    const __half* __restrict__ qkv, __half* __restrict__ att, float* sm)
{
    constexpr int TW = 16 + 2 * R;
    constexpr int NR = TW * TW;

    const int tile = blockIdx.x;
    const int b    = blockIdx.y;
    const int hh   = blockIdx.z & 3;
    const int di   = (R == 1) ? 0 : 1;
    const int tx0  = (tile % 10) * 16;
    const int ty0  = (tile / 10) * 16;
    const int tid  = threadIdx.x;
    const int lx   = tid & 15;
    const int ly   = tid >> 4;
    const int off  = di * 64 + hh * 16;

    const size_t pix = ((size_t)b * H_ + (ty0 + ly)) * W_ + (tx0 + lx);

    // Load q (16 halves = two uint4), convert to 4 float4.
    const uint4 qr  = *(const uint4*)(qkv + pix * 384 + off);
    const uint4 qr2 = *(const uint4*)(qkv + pix * 384 + off + 8);
    const float2 f0 = h2f(qr.x),  f1 = h2f(qr.y),  f2 = h2f(qr.z),  f3 = h2f(qr.w);
    const float2 f4 = h2f(qr2.x), f5 = h2f(qr2.y), f6 = h2f(qr2.z), f7 = h2f(qr2.w);
    const float4 q0 = make_float4(f0.x, f0.y, f1.x, f1.y);
    const float4 q1 = make_float4(f2.x, f2.y, f3.x, f3.y);
    const float4 q2 = make_float4(f4.x, f4.y, f5.x, f5.y);
    const float4 q3 = make_float4(f6.x, f6.y, f7.x, f7.y);

    // Phase 1: K halo tile -> smem (zero fill OOB == reference zero padding).
    #pragma unroll 2
    for (int i = tid; i < NR * 2; i += 256) {
        const int row = i >> 1, h8 = (i & 1) * 8;
        const int lyy = row / TW, lxx = row - lyy * TW;
        const int yy = ty0 + lyy - R, xx = tx0 + lxx - R;
        float4 va = make_float4(0.f,0.f,0.f,0.f), vb = va;
        if (yy >= 0 && yy < H_ && xx >= 0 && xx < W_) {
            const uint4 u = *(const uint4*)(qkv
                + (((size_t)b * H_ + yy) * W_ + xx) * 384 + 128 + off + h8);
            const float2 a = h2f(u.x), c = h2f(u.y), d = h2f(u.z), e = h2f(u.w);
            va = make_float4(a.x, a.y, c.x, c.y);
            vb = make_float4(d.x, d.y, e.x, e.y);
        }
        *(float4*)&sm[row * 20 + h8]     = va;
        *(float4*)&sm[row * 20 + h8 + 4] = vb;
    }
    __syncthreads();

    float s[9];
    #pragma unroll
    for (int ky = 0; ky < 3; ky++)
        #pragma unroll
        for (int kx = 0; kx < 3; kx++) {
            const float* kp = &sm[((ly + ky * R) * TW + (lx + kx * R)) * 20];
            const float4 k0 = *(const float4*)(kp);
            const float4 k1 = *(const float4*)(kp + 4);
            const float4 k2 = *(const float4*)(kp + 8);
            const float4 k3 = *(const float4*)(kp + 12);
            float sc = q0.x*k0.x + q0.y*k0.y + q0.z*k0.z + q0.w*k0.w
                     + q1.x*k1.x + q1.y*k1.y + q1.z*k1.z + q1.w*k1.w
                     + q2.x*k2.x + q2.y*k2.y + q2.z*k2.z + q2.w*k2.w
                     + q3.x*k3.x + q3.y*k3.y + q3.z*k3.z + q3.w*k3.w;
            s[ky * 3 + kx] = sc * 0.25f;
        }

    float sum = 0.f;
    #pragma unroll
    for (int kk = 0; kk < 9; kk++) { s[kk] = fast_exp(s[kk]); sum += s[kk]; }
    const float inv = 1.f / sum;
    #pragma unroll
    for (int kk = 0; kk < 9; kk++) s[kk] *= inv;

    __syncthreads();

    // Phase 2: V halo tile -> same smem.
    #pragma unroll 2
    for (int i = tid; i < NR * 2; i += 256) {
        const int row = i >> 1, h8 = (i & 1) * 8;
        const int lyy = row / TW, lxx = row - lyy * TW;
        const int yy = ty0 + lyy - R, xx = tx0 + lxx - R;
        float4 va = make_float4(0.f,0.f,0.f,0.f), vb = va;
        if (yy >= 0 && yy < H_ && xx >= 0 && xx < W_) {
            const uint4 u = *(const uint4*)(qkv
                + (((size_t)b * H_ + yy) * W_ + xx) * 384 + 256 + off + h8);
            const float2 a = h2f(u.x), c = h2f(u.y), d = h2f(u.z), e = h2f(u.w);
            va = make_float4(a.x, a.y, c.x, c.y);
            vb = make_float4(d.x, d.y, e.x, e.y);
        }
        *(float4*)&sm[row * 20 + h8]     = va;
        *(float4*)&sm[row * 20 + h8 + 4] = vb;
    }
    __syncthreads();

    float4 o0 = {0,0,0,0}, o1 = {0,0,0,0}, o2 = {0,0,0,0}, o3 = {0,0,0,0};
    #pragma unroll
    for (int ky = 0; ky < 3; ky++)
        #pragma unroll
        for (int kx = 0; kx < 3; kx++) {
            const float w = s[ky * 3 + kx];
            const float* vp = &sm[((ly + ky * R) * TW + (lx + kx * R)) * 20];
            const float4 v0 = *(const float4*)(vp);
            const float4 v1 = *(const float4*)(vp + 4);
            const float4 v2 = *(const float4*)(vp + 8);
            const float4 v3 = *(const float4*)(vp + 12);
            o0.x += w*v0.x; o0.y += w*v0.y; o0.z += w*v0.z; o0.w += w*v0.w;
            o1.x += w*v1.x; o1.y += w*v1.y; o1.z += w*v1.z; o1.w += w*v1.w;
            o2.x += w*v2.x; o2.y += w*v2.y; o2.z += w*v2.z; o2.w += w*v2.w;
            o3.x += w*v3.x; o3.y += w*v3.y; o3.z += w*v3.z; o3.w += w*v3.w;
        }

    // Store fp16 (proj GEMM A operand). 16 halves = two uint4.
    uint4 u0, u1;
    u0.x = pack_h2(o0.x, o0.y); u0.y = pack_h2(o0.z, o0.w);
    u0.z = pack_h2(o1.x, o1.y); u0.w = pack_h2(o1.z, o1.w);
    u1.x = pack_h2(o2.x, o2.y); u1.y = pack_h2(o2.z, o2.w);
    u1.z = pack_h2(o3.x, o3.y); u1.w = pack_h2(o3.z, o3.w);
    uint4* op = (uint4*)(att + pix * 128 + off);
    op[0] = u0; op[1] = u1;
}

// One launch covering both dilations: grid z in 0..7, di = z>>2, head = z&3.
__global__ __launch_bounds__(256) void attn_all(
    const __half* __restrict__ qkv, __half* __restrict__ att)
{
    __shared__ float sm[20 * 20 * 20];   // sized for r=2 halo (400 rows x 20)
    if (blockIdx.z < 4) attn_body<1>(qkv, att, sm);
    else                attn_body<2>(qkv, att, sm);
}

// ---------------------------------------------------------------------------
extern "C" void kernel_launch(void* const* d_in, const int* in_sizes, int n_in,
                              void* d_out, int out_size)
{
    const float* x      = (const float*)d_in[0];
    const float* qkv_w  = (const float*)d_in[1];
    const float* proj_w = (const float*)d_in[2];
    const float* proj_b = (const float*)d_in[3];
    float* out = (float*)d_out;

    __half *qkvbuf, *xh, *attbuf, *wq, *wp;
    cudaGetSymbolAddress((void**)&qkvbuf, g_qkv);
    cudaGetSymbolAddress((void**)&xh, g_xh);
    cudaGetSymbolAddress((void**)&attbuf, g_att);
    cudaGetSymbolAddress((void**)&wq, g_wq);
    cudaGetSymbolAddress((void**)&wp, g_wp);

    // 0) Convert x + weights to fp16 (one vectorized launch).
    prep<<<(XV + QV + PV) / 256, 256>>>(
        (const float4*)x, (const float4*)qkv_w, (const float4*)proj_w,
        (uint2*)xh, (uint2*)wq, (uint2*)wp);

    // 1) QKV projection: [51200,128] x [384,128]^T -> [51200,384] fp16 out.
    dim3 g1(NPIX / 128, 384 / 128);
    tgemm_h<true><<<g1, 256>>>(xh, wq, nullptr, qkvbuf, NPIX, 384);

    // 2) Dilated neighborhood attention (both dilations, one launch; fp16 out)
    dim3 ga(100, 2, 8);
    attn_all<<<ga, 256>>>(qkvbuf, attbuf);

    // 3) Output projection + bias: [51200,128] x [128,128]^T -> fp32 out.
    dim3 g3(NPIX / 128, 128 / 128);
    tgemm_h<false><<<g3, 256>>>(attbuf, wp, proj_b, out, NPIX, 128);
}